// round 4
// baseline (speedup 1.0000x reference)
#include <cuda_runtime.h>

#define BATCH 64
#define CIN   96
#define CHID  256
#define COUT  80
#define TLEN  2048

// ---- scratch (allocation-free rule: __device__ globals) ----
static __device__ unsigned g_xbits[(size_t)BATCH * TLEN * 4];          // 2 MiB  [b][t][{m0,m1,m2,pad}]
static __device__ unsigned g_s1bits[(size_t)BATCH * TLEN * (CHID/32)]; // 4 MiB  [b][t][8]

// =====================================================================
// K0: build 96-bit input-activity masks per (b,t).
// Warp lanes = consecutive t -> all 96 LDGs coalesced. uint4 store.
// =====================================================================
__global__ __launch_bounds__(256) void k0_xbits(const float* __restrict__ x) {
    const int gid = blockIdx.x * 256 + threadIdx.x;   // 0 .. 64*2048-1
    const int b = gid >> 11;
    const int t = gid & 2047;
    const float* xp = x + (size_t)b * CIN * TLEN + t;
    unsigned m0 = 0, m1 = 0, m2 = 0;
    #pragma unroll
    for (int i = 0; i < 32; i++) if (__ldg(xp + (size_t)i * TLEN) != 0.0f)          m0 |= 1u << i;
    #pragma unroll
    for (int i = 0; i < 32; i++) if (__ldg(xp + (size_t)(i + 32) * TLEN) != 0.0f)   m1 |= 1u << i;
    #pragma unroll
    for (int i = 0; i < 32; i++) if (__ldg(xp + (size_t)(i + 64) * TLEN) != 0.0f)   m2 |= 1u << i;
    *(uint4*)&g_xbits[(size_t)gid * 4] = make_uint4(m0, m1, m2, 0u);
}

// =====================================================================
// F1: fused layer-1 sparse GEMM + LIF scan.
// CTA = (o-half, b): 128 CTAs x 128 threads, thread owns one o for all T.
// Per 128-step block: build zero-padded ascending index lists (uint16
// word-offsets i*128, dummy row 96 = zeros), then per PAIR of steps run
// two interleaved ascending FADD chains (independent accs) + serial LIF.
// Bit-exact: ascending-i sums, v = fma(v,0.95,z), hard reset.
// =====================================================================
#define TB1 128
__global__ __launch_bounds__(128) void f1_layer1(const float* __restrict__ W1,
                                                 float* __restrict__ out) {
    extern __shared__ char sm[];
    float*          w1h    = (float*)sm;                     // [97][128]
    unsigned short* lists  = (unsigned short*)(sm + 49664);  // [128][104]
    int*            counts = (int*)(sm + 76288);             // [128]

    const int tid  = threadIdx.x;
    const int o0   = blockIdx.x * 128;
    const int b    = blockIdx.y;
    const int lane = tid & 31;

    // W1 [256][96] row-major -> w1h[i*128 + ol]; dummy row i=96 zeros
    for (int idx = tid; idx < 128 * CIN; idx += 128) {
        int ol = idx / CIN, i = idx % CIN;
        w1h[i * 128 + ol] = W1[(size_t)(o0 + ol) * CIN + i];
    }
    w1h[96 * 128 + tid] = 0.0f;

    float* so = out + ((size_t)b * CHID + o0 + tid) * TLEN;
    unsigned* bwbase = g_s1bits + (size_t)b * TLEN * 8 + ((unsigned)(o0 + tid) >> 5);

    float v = 0.0f;
    unsigned keep = 0;
    float sv[4];

    for (int blk = 0; blk < TLEN / TB1; blk++) {
        const int t0 = blk * TB1;
        __syncthreads();   // protect lists from previous block's readers
        {   // build list for step t0+tid (ascending i)
            uint4 mw = *(const uint4*)&g_xbits[(size_t)(b * TLEN + t0 + tid) * 4];
            unsigned short* L = lists + tid * 104;
            int c = 0;
            unsigned m = mw.x;
            while (m) { int k = __ffs(m) - 1; m &= m - 1; L[c++] = (unsigned short)(k * 128); }
            m = mw.y;
            while (m) { int k = __ffs(m) - 1; m &= m - 1; L[c++] = (unsigned short)((k + 32) * 128); }
            m = mw.z;
            while (m) { int k = __ffs(m) - 1; m &= m - 1; L[c++] = (unsigned short)((k + 64) * 128); }
            while (c & 7) L[c++] = (unsigned short)(96 * 128);
            counts[tid] = c;
        }
        __syncthreads();

        for (int tt = 0; tt < TB1; tt += 2) {
            const unsigned short* L0 = lists + tt * 104;
            const unsigned short* L1 = L0 + 104;
            const int c0 = counts[tt], c1 = counts[tt + 1];
            const int cmin = c0 < c1 ? c0 : c1;
            float a0 = 0.0f, a1 = 0.0f;
            int p = 0;
            for (; p < cmin; p += 8) {             // two interleaved chains
                uint4 u = *(const uint4*)(L0 + p);
                uint4 w = *(const uint4*)(L1 + p);
                a0 += w1h[(u.x & 0xffff) + tid];  a1 += w1h[(w.x & 0xffff) + tid];
                a0 += w1h[(u.x >> 16)    + tid];  a1 += w1h[(w.x >> 16)    + tid];
                a0 += w1h[(u.y & 0xffff) + tid];  a1 += w1h[(w.y & 0xffff) + tid];
                a0 += w1h[(u.y >> 16)    + tid];  a1 += w1h[(w.y >> 16)    + tid];
                a0 += w1h[(u.z & 0xffff) + tid];  a1 += w1h[(w.z & 0xffff) + tid];
                a0 += w1h[(u.z >> 16)    + tid];  a1 += w1h[(w.z >> 16)    + tid];
                a0 += w1h[(u.w & 0xffff) + tid];  a1 += w1h[(w.w & 0xffff) + tid];
                a0 += w1h[(u.w >> 16)    + tid];  a1 += w1h[(w.w >> 16)    + tid];
            }
            for (; p < c0; p += 8) {
                uint4 u = *(const uint4*)(L0 + p);
                a0 += w1h[(u.x & 0xffff) + tid];  a0 += w1h[(u.x >> 16) + tid];
                a0 += w1h[(u.y & 0xffff) + tid];  a0 += w1h[(u.y >> 16) + tid];
                a0 += w1h[(u.z & 0xffff) + tid];  a0 += w1h[(u.z >> 16) + tid];
                a0 += w1h[(u.w & 0xffff) + tid];  a0 += w1h[(u.w >> 16) + tid];
            }
            for (; p < c1; p += 8) {
                uint4 w = *(const uint4*)(L1 + p);
                a1 += w1h[(w.x & 0xffff) + tid];  a1 += w1h[(w.x >> 16) + tid];
                a1 += w1h[(w.y & 0xffff) + tid];  a1 += w1h[(w.y >> 16) + tid];
                a1 += w1h[(w.z & 0xffff) + tid];  a1 += w1h[(w.z >> 16) + tid];
                a1 += w1h[(w.w & 0xffff) + tid];  a1 += w1h[(w.w >> 16) + tid];
            }
            // LIF (strictly t-ascending)
            v = __fmaf_rn(v, 0.95f, a0);
            bool s0 = (v >= 1.0f);
            v = s0 ? 0.0f : v;
            v = __fmaf_rn(v, 0.95f, a1);
            bool s1 = (v >= 1.0f);
            v = s1 ? 0.0f : v;
            sv[tt & 3]       = s0 ? 1.0f : 0.0f;
            sv[(tt + 1) & 3] = s1 ? 1.0f : 0.0f;
            unsigned b0 = __ballot_sync(0xffffffffu, s0);
            unsigned b1 = __ballot_sync(0xffffffffu, s1);
            keep = (lane == (tt & 31))       ? b0 : keep;
            keep = (lane == ((tt + 1) & 31)) ? b1 : keep;
            if (((tt + 1) & 3) == 3)
                *(float4*)(so + t0 + (tt & ~3)) = make_float4(sv[0], sv[1], sv[2], sv[3]);
            if (((tt + 1) & 31) == 31)
                bwbase[(size_t)(t0 + (tt & ~31) + lane) * 8] = keep;
        }
    }
}

// =====================================================================
// F2: fused layer-2 sparse GEMM + LIF scan.
// CTA = (j-half of 40, b): 128 CTAs x 64 threads (40 active for compute).
// Lists from g_s1bits (ascending o), entries o*40 (word offsets), dummy
// row o=256 zeros. Same paired-chain structure. No bit output.
// =====================================================================
#define TB2 64
__global__ __launch_bounds__(64) void f2_layer2(const float* __restrict__ W2,
                                                float* __restrict__ out) {
    extern __shared__ char sm[];
    float*          w2h    = (float*)sm;                     // [257][40]
    unsigned short* lists  = (unsigned short*)(sm + 41120);  // [64][264]
    int*            counts = (int*)(sm + 74912);             // [64]

    const int tid = threadIdx.x;
    const int j0  = blockIdx.x * 40;
    const int b   = blockIdx.y;

    // W2 [80][256] row-major -> w2h[o*40 + r]; dummy row o=256 zeros
    for (int idx = tid; idx < 40 * CHID; idx += 64) {
        int r = idx / CHID, o = idx % CHID;
        w2h[o * 40 + r] = W2[(size_t)(j0 + r) * CHID + o];
    }
    for (int idx = tid; idx < 40; idx += 64) w2h[256 * 40 + idx] = 0.0f;

    const bool act = (tid < 40);
    float* so = out + (size_t)BATCH * CHID * TLEN
                    + ((size_t)b * COUT + j0 + (act ? tid : 39)) * TLEN;

    float v = 0.0f;
    float sv[4];

    for (int blk = 0; blk < TLEN / TB2; blk++) {
        const int t0 = blk * TB2;
        __syncthreads();
        {   // build list for step t0+tid from spike bits (ascending o)
            const unsigned* sb = g_s1bits + (size_t)(b * TLEN + t0 + tid) * 8;
            unsigned short* L = lists + tid * 264;
            int c = 0;
            #pragma unroll
            for (int w = 0; w < 8; w++) {
                unsigned m = sb[w];
                while (m) {
                    int k = __ffs(m) - 1;
                    m &= m - 1;
                    L[c++] = (unsigned short)((w * 32 + k) * 40);
                }
            }
            while (c & 7) L[c++] = (unsigned short)(256 * 40);
            counts[tid] = c;
        }
        __syncthreads();

        const int r = act ? tid : 39;   // idle lanes shadow j=39 (no store)
        for (int tt = 0; tt < TB2; tt += 2) {
            const unsigned short* L0 = lists + tt * 264;
            const unsigned short* L1 = L0 + 264;
            const int c0 = counts[tt], c1 = counts[tt + 1];
            const int cmin = c0 < c1 ? c0 : c1;
            float a0 = 0.0f, a1 = 0.0f;
            int p = 0;
            for (; p < cmin; p += 8) {
                uint4 u = *(const uint4*)(L0 + p);
                uint4 w = *(const uint4*)(L1 + p);
                a0 += w2h[(u.x & 0xffff) + r];  a1 += w2h[(w.x & 0xffff) + r];
                a0 += w2h[(u.x >> 16)    + r];  a1 += w2h[(w.x >> 16)    + r];
                a0 += w2h[(u.y & 0xffff) + r];  a1 += w2h[(w.y & 0xffff) + r];
                a0 += w2h[(u.y >> 16)    + r];  a1 += w2h[(w.y >> 16)    + r];
                a0 += w2h[(u.z & 0xffff) + r];  a1 += w2h[(w.z & 0xffff) + r];
                a0 += w2h[(u.z >> 16)    + r];  a1 += w2h[(w.z >> 16)    + r];
                a0 += w2h[(u.w & 0xffff) + r];  a1 += w2h[(w.w & 0xffff) + r];
                a0 += w2h[(u.w >> 16)    + r];  a1 += w2h[(w.w >> 16)    + r];
            }
            for (; p < c0; p += 8) {
                uint4 u = *(const uint4*)(L0 + p);
                a0 += w2h[(u.x & 0xffff) + r];  a0 += w2h[(u.x >> 16) + r];
                a0 += w2h[(u.y & 0xffff) + r];  a0 += w2h[(u.y >> 16) + r];
                a0 += w2h[(u.z & 0xffff) + r];  a0 += w2h[(u.z >> 16) + r];
                a0 += w2h[(u.w & 0xffff) + r];  a0 += w2h[(u.w >> 16) + r];
            }
            for (; p < c1; p += 8) {
                uint4 w = *(const uint4*)(L1 + p);
                a1 += w2h[(w.x & 0xffff) + r];  a1 += w2h[(w.x >> 16) + r];
                a1 += w2h[(w.y & 0xffff) + r];  a1 += w2h[(w.y >> 16) + r];
                a1 += w2h[(w.z & 0xffff) + r];  a1 += w2h[(w.z >> 16) + r];
                a1 += w2h[(w.w & 0xffff) + r];  a1 += w2h[(w.w >> 16) + r];
            }
            v = __fmaf_rn(v, 0.95f, a0);
            bool s0 = (v >= 1.0f);
            v = s0 ? 0.0f : v;
            v = __fmaf_rn(v, 0.95f, a1);
            bool s1 = (v >= 1.0f);
            v = s1 ? 0.0f : v;
            sv[tt & 3]       = s0 ? 1.0f : 0.0f;
            sv[(tt + 1) & 3] = s1 ? 1.0f : 0.0f;
            if (((tt + 1) & 3) == 3 && act)
                *(float4*)(so + t0 + (tt & ~3)) = make_float4(sv[0], sv[1], sv[2], sv[3]);
        }
    }
}

// =====================================================================
extern "C" void kernel_launch(void* const* d_in, const int* in_sizes, int n_in,
                              void* d_out, int out_size) {
    const float* x  = (const float*)d_in[0];   // [64, 96, 2048]
    const float* W1 = (const float*)d_in[1];   // [256, 96]
    const float* W2 = (const float*)d_in[2];   // [80, 256]
    float* out = (float*)d_out;                // spk1 ++ spk2

    const int smem1 = 49664 + 26624 + 512;     // 76800
    const int smem2 = 41120 + 33792 + 256;     // 75168
    cudaFuncSetAttribute(f1_layer1, cudaFuncAttributeMaxDynamicSharedMemorySize, smem1);
    cudaFuncSetAttribute(f2_layer2, cudaFuncAttributeMaxDynamicSharedMemorySize, smem2);

    k0_xbits<<<(BATCH * TLEN) / 256, 256>>>(x);
    f1_layer1<<<dim3(2, BATCH), 128, smem1>>>(W1, out);
    f2_layer2<<<dim3(2, BATCH), 64, smem2>>>(W2, out);
}

// round 5
// speedup vs baseline: 2.1827x; 2.1827x over previous
#include <cuda_runtime.h>

#define BATCH 64
#define CIN   96
#define CHID  256
#define COUT  80
#define TLEN  2048

// ---- scratch (allocation-free rule: __device__ globals) ----
static __device__ float    g_z1[(size_t)BATCH * TLEN * CHID];          // 128 MiB
static __device__ float    g_z2[(size_t)BATCH * TLEN * COUT];          // 40 MiB
static __device__ unsigned g_xbits[(size_t)BATCH * TLEN * 4];          // 2 MiB
static __device__ unsigned g_s1bits[(size_t)BATCH * TLEN * (CHID/32)]; // 4 MiB

// =====================================================================
// K0: build 96-bit input-activity masks per (b,t). Coalesced LDGs.
// =====================================================================
__global__ __launch_bounds__(256) void k0_xbits(const float* __restrict__ x) {
    const int gid = blockIdx.x * 256 + threadIdx.x;   // 0 .. 64*2048-1
    const int b = gid >> 11;
    const int t = gid & 2047;
    const float* xp = x + (size_t)b * CIN * TLEN + t;
    unsigned m0 = 0, m1 = 0, m2 = 0;
    #pragma unroll
    for (int i = 0; i < 32; i++) if (__ldg(xp + (size_t)i * TLEN) != 0.0f)        m0 |= 1u << i;
    #pragma unroll
    for (int i = 0; i < 32; i++) if (__ldg(xp + (size_t)(i + 32) * TLEN) != 0.0f) m1 |= 1u << i;
    #pragma unroll
    for (int i = 0; i < 32; i++) if (__ldg(xp + (size_t)(i + 64) * TLEN) != 0.0f) m2 |= 1u << i;
    *(uint4*)&g_xbits[(size_t)gid * 4] = make_uint4(m0, m1, m2, 0u);
}

// =====================================================================
// K1: layer-1 sparse GEMM. z1[b][t][o] = sum_{i active, ascending} W1[o][i]
// CTA = (t-chunk 128, b); 256 threads; thread owns 4 adjacent o (LDS.128,
// contiguous 512B per warp -> conflict-free). Lists = uint32 BYTE offsets
// i*1024 (row stride 256 floats), zero-padded to x4 (dummy row 96 = 0).
// 4 independent FADD chains; bit-exact ascending-i order per o.
// =====================================================================
#define K1_T 128
__global__ __launch_bounds__(256) void k1_gemm1(const float* __restrict__ W1) {
    extern __shared__ char sm[];
    float*    w1t    = (float*)sm;                   // [97][256] = 99328 B
    unsigned* lists  = (unsigned*)(sm + 99328);      // [128][104] u32 = 53248 B
    int*      counts = (int*)(sm + 152576);          // [128]

    const int tid = threadIdx.x;
    const int t0  = blockIdx.x * K1_T;
    const int b   = blockIdx.y;

    // W1 [256][96] row-major -> w1t[i*256 + o]; dummy row i=96 zeros
    for (int idx = tid; idx < CHID * CIN; idx += 256) {
        int o = idx / CIN, i = idx % CIN;
        w1t[i * 256 + o] = W1[idx];
    }
    w1t[96 * 256 + tid] = 0.0f;

    if (tid < K1_T) {  // build ascending byte-offset list for step t0+tid
        uint4 mw = *(const uint4*)&g_xbits[(size_t)(b * TLEN + t0 + tid) * 4];
        unsigned* L = lists + tid * 104;
        int c = 0;
        unsigned m = mw.x;
        while (m) { int k = __ffs(m) - 1; m &= m - 1; L[c++] = (unsigned)(k << 10); }
        m = mw.y;
        while (m) { int k = __ffs(m) - 1; m &= m - 1; L[c++] = (unsigned)((k + 32) << 10); }
        m = mw.z;
        while (m) { int k = __ffs(m) - 1; m &= m - 1; L[c++] = (unsigned)((k + 64) << 10); }
        while (c & 3) L[c++] = (unsigned)(96 << 10);
        counts[tid] = c;
    }
    __syncthreads();

    const int grp = tid >> 6;          // 0..3: step interleave
    const int o   = (tid & 63) * 4;    // 4 adjacent outputs
    const char* wb = (const char*)w1t + o * 4;
    float* zp = g_z1 + ((size_t)b * TLEN + t0) * CHID + o;

    for (int tt = grp; tt < K1_T; tt += 4) {
        const unsigned* L = lists + tt * 104;
        const int cnt = counts[tt];
        float a0 = 0.0f, a1 = 0.0f, a2 = 0.0f, a3 = 0.0f;
        for (int p = 0; p < cnt; p += 4) {
            uint4 e = *(const uint4*)(L + p);
            float4 w0 = *(const float4*)(wb + e.x);
            float4 w1 = *(const float4*)(wb + e.y);
            float4 w2 = *(const float4*)(wb + e.z);
            float4 w3 = *(const float4*)(wb + e.w);
            a0 += w0.x; a1 += w0.y; a2 += w0.z; a3 += w0.w;
            a0 += w1.x; a1 += w1.y; a2 += w1.z; a3 += w1.w;
            a0 += w2.x; a1 += w2.y; a2 += w2.z; a3 += w2.w;
            a0 += w3.x; a1 += w3.y; a2 += w3.z; a3 += w3.w;
        }
        *(float4*)(zp + (size_t)tt * CHID) = make_float4(a0, a1, a2, a3);
    }
}

// =====================================================================
// LIF batch processors.  v = fma(v, 0.95f, z) — matches XLA contraction.
// =====================================================================
__device__ __forceinline__ void proc32_bits(float& v, const float (&z)[32],
                                            int tbase, float* __restrict__ so,
                                            unsigned* __restrict__ bw, int lane) {
    unsigned keep = 0;
    #pragma unroll
    for (int u8 = 0; u8 < 32; u8 += 8) {
        float sv[8];
        #pragma unroll
        for (int u = 0; u < 8; u++) {
            const int st = u8 + u;
            v = __fmaf_rn(v, 0.95f, z[st]);
            bool sp = (v >= 1.0f);
            sv[u] = sp ? 1.0f : 0.0f;
            unsigned bal = __ballot_sync(0xffffffffu, sp);
            keep = (lane == st) ? bal : keep;
            v = sp ? 0.0f : v;
        }
        *(float4*)(so + tbase + u8)     = make_float4(sv[0], sv[1], sv[2], sv[3]);
        *(float4*)(so + tbase + u8 + 4) = make_float4(sv[4], sv[5], sv[6], sv[7]);
    }
    bw[(size_t)(tbase + lane) * (CHID/32)] = keep;  // one scattered STG per 32 steps
}

__device__ __forceinline__ void proc32(float& v, const float (&z)[32],
                                       int tbase, float* __restrict__ so) {
    #pragma unroll
    for (int u8 = 0; u8 < 32; u8 += 8) {
        float sv[8];
        #pragma unroll
        for (int u = 0; u < 8; u++) {
            v = __fmaf_rn(v, 0.95f, z[u8 + u]);
            bool sp = (v >= 1.0f);
            sv[u] = sp ? 1.0f : 0.0f;
            v = sp ? 0.0f : v;
        }
        *(float4*)(so + tbase + u8)     = make_float4(sv[0], sv[1], sv[2], sv[3]);
        *(float4*)(so + tbase + u8 + 4) = make_float4(sv[4], sv[5], sv[6], sv[7]);
    }
}

// =====================================================================
// K2: layer-1 LIF scan. 16384 threads, block=64 (256 CTAs).
// 4 rotating 32-step register buffers (prefetch distance 3).
// =====================================================================
#define LD32(dst, zp, t) { _Pragma("unroll") \
    for (int u = 0; u < 32; u++) dst[u] = __ldg(zp + (size_t)((t) + u) * CHID); }

__global__ __launch_bounds__(64) void k2_scan1(float* __restrict__ out) {
    const int gid  = blockIdx.x * 64 + threadIdx.x;   // 0..16383
    const int b    = gid >> 8;
    const int o    = gid & 255;
    const int lane = o & 31;
    const float* z  = g_z1 + (size_t)b * TLEN * CHID + o;
    float*       so = out + ((size_t)b * CHID + o) * TLEN;
    unsigned*    bw = g_s1bits + (size_t)b * TLEN * (CHID/32) + (o >> 5);

    float A[32], B[32], C[32], D[32];
    float v = 0.0f;
    LD32(A, z, 0); LD32(B, z, 32); LD32(C, z, 64);

    for (int bi = 0; bi < 64; bi += 4) {
        const int t = bi * 32;
        if (bi + 3 < 64) LD32(D, z, t + 96);
        proc32_bits(v, A, t, so, bw, lane);
        if (bi + 4 < 64) LD32(A, z, t + 128);
        proc32_bits(v, B, t + 32, so, bw, lane);
        if (bi + 5 < 64) LD32(B, z, t + 160);
        proc32_bits(v, C, t + 64, so, bw, lane);
        if (bi + 6 < 64) LD32(C, z, t + 192);
        proc32_bits(v, D, t + 96, so, bw, lane);
    }
}

// =====================================================================
// K3: layer-2 sparse GEMM from spike bits. CTA = (t-chunk 64, b);
// 384 threads = 4 groups x 96 (3 full warps -> warp-uniform masks).
// uint32 BYTE-offset lists (o*324, w2t stride 81 floats), dummy row 256.
// Two timesteps per iteration -> 2 independent FADD chains.
// =====================================================================
#define K3_T 64
__global__ __launch_bounds__(384) void k3_gemm2(const float* __restrict__ W2) {
    extern __shared__ char sm[];
    float*    w2t    = (float*)sm;                   // [257][81]+pad = 83344 B
    unsigned* lists  = (unsigned*)(sm + 83344);      // [64][264] u32 = 67584 B
    int*      counts = (int*)(sm + 150928);          // [64]

    const int tid = threadIdx.x;
    const int t0  = blockIdx.x * K3_T;
    const int b   = blockIdx.y;

    // W2 [80][256] row-major -> w2t[o*81 + j]; dummy row o=256 zeros
    for (int idx = tid; idx < COUT * CHID; idx += 384) {
        int j = idx / CHID, o = idx % CHID;
        w2t[o * 81 + j] = W2[idx];
    }
    for (int idx = tid; idx < 100; idx += 384) w2t[256 * 81 + idx] = 0.0f;

    if (tid < K3_T) {  // build ascending o byte-offset list for step t0+tid
        const unsigned* sb = g_s1bits + (size_t)(b * TLEN + t0 + tid) * 8;
        unsigned* L = lists + tid * 264;
        int c = 0;
        #pragma unroll
        for (int w = 0; w < 8; w++) {
            unsigned m = sb[w];
            while (m) {
                int k = __ffs(m) - 1;
                m &= m - 1;
                L[c++] = (unsigned)(((w << 5) + k) * 324);
            }
        }
        while (c & 3) L[c++] = (unsigned)(256 * 324);
        counts[tid] = c;
    }
    __syncthreads();

    const int grp = tid / 96;            // 0..3 (3 full warps each)
    const int r   = tid % 96;            // j = r (r>=80 compute-only shadows)
    const char* wb = (const char*)w2t + r * 4;
    float* zo = g_z2 + ((size_t)b * TLEN + t0) * COUT;

    for (int q = grp; q < K3_T / 2; q += 4) {
        const int tt = 2 * q;
        const unsigned* L0 = lists + tt * 264;
        const unsigned* L1 = L0 + 264;
        const int c0 = counts[tt], c1 = counts[tt + 1];
        const int cmin = c0 < c1 ? c0 : c1;
        float a0 = 0.0f, a1 = 0.0f;
        int p = 0;
        for (; p < cmin; p += 4) {         // interleaved chains
            uint4 e0 = *(const uint4*)(L0 + p);
            uint4 e1 = *(const uint4*)(L1 + p);
            a0 += *(const float*)(wb + e0.x);  a1 += *(const float*)(wb + e1.x);
            a0 += *(const float*)(wb + e0.y);  a1 += *(const float*)(wb + e1.y);
            a0 += *(const float*)(wb + e0.z);  a1 += *(const float*)(wb + e1.z);
            a0 += *(const float*)(wb + e0.w);  a1 += *(const float*)(wb + e1.w);
        }
        for (; p < c0; p += 4) {
            uint4 e0 = *(const uint4*)(L0 + p);
            a0 += *(const float*)(wb + e0.x);  a0 += *(const float*)(wb + e0.y);
            a0 += *(const float*)(wb + e0.z);  a0 += *(const float*)(wb + e0.w);
        }
        for (; p < c1; p += 4) {
            uint4 e1 = *(const uint4*)(L1 + p);
            a1 += *(const float*)(wb + e1.x);  a1 += *(const float*)(wb + e1.y);
            a1 += *(const float*)(wb + e1.z);  a1 += *(const float*)(wb + e1.w);
        }
        if (r < COUT) {
            zo[(size_t)tt * COUT + r]       = a0;
            zo[(size_t)(tt + 1) * COUT + r] = a1;
        }
    }
}

// =====================================================================
// K4: layer-2 LIF scan. 5120 threads, block=32 (160 CTAs).
// =====================================================================
#define LD32B(dst, zp, t) { _Pragma("unroll") \
    for (int u = 0; u < 32; u++) dst[u] = __ldg(zp + (size_t)((t) + u) * COUT); }

__global__ __launch_bounds__(32) void k4_scan2(float* __restrict__ out) {
    const int gid = blockIdx.x * 32 + threadIdx.x;   // 0..5119
    const int b = gid / COUT;
    const int j = gid % COUT;
    const float* z  = g_z2 + (size_t)b * TLEN * COUT + j;
    float*       so = out + (size_t)BATCH * CHID * TLEN
                          + ((size_t)b * COUT + j) * TLEN;

    float A[32], B[32], C[32], D[32];
    float v = 0.0f;
    LD32B(A, z, 0); LD32B(B, z, 32); LD32B(C, z, 64);

    for (int bi = 0; bi < 64; bi += 4) {
        const int t = bi * 32;
        if (bi + 3 < 64) LD32B(D, z, t + 96);
        proc32(v, A, t, so);
        if (bi + 4 < 64) LD32B(A, z, t + 128);
        proc32(v, B, t + 32, so);
        if (bi + 5 < 64) LD32B(B, z, t + 160);
        proc32(v, C, t + 64, so);
        if (bi + 6 < 64) LD32B(C, z, t + 192);
        proc32(v, D, t + 96, so);
    }
}

// =====================================================================
extern "C" void kernel_launch(void* const* d_in, const int* in_sizes, int n_in,
                              void* d_out, int out_size) {
    const float* x  = (const float*)d_in[0];   // [64, 96, 2048]
    const float* W1 = (const float*)d_in[1];   // [256, 96]
    const float* W2 = (const float*)d_in[2];   // [80, 256]
    float* out = (float*)d_out;                // spk1 ++ spk2

    const int smem1 = 99328 + 53248 + 512;     // 153088
    const int smem3 = 83344 + 67584 + 256;     // 151184
    cudaFuncSetAttribute(k1_gemm1, cudaFuncAttributeMaxDynamicSharedMemorySize, smem1);
    cudaFuncSetAttribute(k3_gemm2, cudaFuncAttributeMaxDynamicSharedMemorySize, smem3);

    k0_xbits<<<(BATCH * TLEN) / 256, 256>>>(x);
    k1_gemm1<<<dim3(TLEN / K1_T, BATCH), 256, smem1>>>(W1);
    k2_scan1<<<(BATCH * CHID) / 64, 64>>>(out);
    k3_gemm2<<<dim3(TLEN / K3_T, BATCH), 384, smem3>>>(W2);
    k4_scan2<<<(BATCH * COUT) / 32, 32>>>(out);
}

// round 6
// speedup vs baseline: 2.3944x; 1.0970x over previous
#include <cuda_runtime.h>

#define BATCH 64
#define CIN   96
#define CHID  256
#define COUT  80
#define TLEN  2048

// ---- scratch (allocation-free rule: __device__ globals) ----
static __device__ float    g_z1[(size_t)BATCH * TLEN * CHID];          // 128 MiB
static __device__ float    g_z2[(size_t)BATCH * TLEN * COUT];          // 40 MiB
static __device__ unsigned g_xbits[(size_t)BATCH * TLEN * 4];          // 2 MiB
static __device__ unsigned g_s1bits[(size_t)BATCH * TLEN * (CHID/32)]; // 4 MiB

// =====================================================================
// K0: build 96-bit input-activity masks per (b,t). Coalesced LDGs.
// =====================================================================
__global__ __launch_bounds__(256) void k0_xbits(const float* __restrict__ x) {
    const int gid = blockIdx.x * 256 + threadIdx.x;   // 0 .. 64*2048-1
    const int b = gid >> 11;
    const int t = gid & 2047;
    const float* xp = x + (size_t)b * CIN * TLEN + t;
    unsigned m0 = 0, m1 = 0, m2 = 0;
    #pragma unroll
    for (int i = 0; i < 32; i++) if (__ldg(xp + (size_t)i * TLEN) != 0.0f)        m0 |= 1u << i;
    #pragma unroll
    for (int i = 0; i < 32; i++) if (__ldg(xp + (size_t)(i + 32) * TLEN) != 0.0f) m1 |= 1u << i;
    #pragma unroll
    for (int i = 0; i < 32; i++) if (__ldg(xp + (size_t)(i + 64) * TLEN) != 0.0f) m2 |= 1u << i;
    *(uint4*)&g_xbits[(size_t)gid * 4] = make_uint4(m0, m1, m2, 0u);
}

// =====================================================================
// K1: layer-1 sparse GEMM. z1[b][t][o] = sum_{i active, ascending} W1[o][i]
// CTA = (t-chunk 128, b); 1024 threads (32 warps -> latency hidden at
// 1 CTA/SM). Thread owns 4 adjacent o (LDS.128); 16 groups of 2 warps
// each cover all 256 o for 8 steps. Lists = uint32 BYTE offsets i*1024,
// zero-padded to x4 (dummy row 96 = 0). List reads warp-uniform
// (broadcast). Bit-exact ascending-i order per o.
// =====================================================================
#define K1_T 128
__global__ __launch_bounds__(1024) void k1_gemm1(const float* __restrict__ W1) {
    extern __shared__ char sm[];
    float*    w1t    = (float*)sm;                   // [97][256] = 99328 B
    unsigned* lists  = (unsigned*)(sm + 99328);      // [128][104] u32 = 53248 B
    int*      counts = (int*)(sm + 152576);          // [128]

    const int tid = threadIdx.x;
    const int t0  = blockIdx.x * K1_T;
    const int b   = blockIdx.y;

    // W1 [256][96] row-major -> w1t[i*256 + o]; dummy row i=96 zeros
    for (int idx = tid; idx < CHID * CIN; idx += 1024) {
        int o = idx / CIN, i = idx % CIN;
        w1t[i * 256 + o] = W1[idx];
    }
    if (tid < 256) w1t[96 * 256 + tid] = 0.0f;

    if (tid < K1_T) {  // build ascending byte-offset list for step t0+tid
        uint4 mw = *(const uint4*)&g_xbits[(size_t)(b * TLEN + t0 + tid) * 4];
        unsigned* L = lists + tid * 104;
        int c = 0;
        unsigned m = mw.x;
        while (m) { int k = __ffs(m) - 1; m &= m - 1; L[c++] = (unsigned)(k << 10); }
        m = mw.y;
        while (m) { int k = __ffs(m) - 1; m &= m - 1; L[c++] = (unsigned)((k + 32) << 10); }
        m = mw.z;
        while (m) { int k = __ffs(m) - 1; m &= m - 1; L[c++] = (unsigned)((k + 64) << 10); }
        while (c & 3) L[c++] = (unsigned)(96 << 10);
        counts[tid] = c;
    }
    __syncthreads();

    const int grp = tid >> 6;          // 0..15: step interleave (2 warps each)
    const int o   = (tid & 63) * 4;    // 4 adjacent outputs
    const char* wb = (const char*)w1t + o * 4;
    float* zp = g_z1 + ((size_t)b * TLEN + t0) * CHID + o;

    for (int tt = grp; tt < K1_T; tt += 16) {
        const unsigned* L = lists + tt * 104;
        const int cnt = counts[tt];
        float a0 = 0.0f, a1 = 0.0f, a2 = 0.0f, a3 = 0.0f;
        for (int p = 0; p < cnt; p += 4) {
            uint4 e = *(const uint4*)(L + p);
            float4 w0 = *(const float4*)(wb + e.x);
            float4 w1 = *(const float4*)(wb + e.y);
            float4 w2 = *(const float4*)(wb + e.z);
            float4 w3 = *(const float4*)(wb + e.w);
            a0 += w0.x; a1 += w0.y; a2 += w0.z; a3 += w0.w;
            a0 += w1.x; a1 += w1.y; a2 += w1.z; a3 += w1.w;
            a0 += w2.x; a1 += w2.y; a2 += w2.z; a3 += w2.w;
            a0 += w3.x; a1 += w3.y; a2 += w3.z; a3 += w3.w;
        }
        *(float4*)(zp + (size_t)tt * CHID) = make_float4(a0, a1, a2, a3);
    }
}

// =====================================================================
// LIF batch processors.  v = fma(v, 0.95f, z) — matches XLA contraction.
// =====================================================================
__device__ __forceinline__ void proc32_bits(float& v, const float (&z)[32],
                                            int tbase, float* __restrict__ so,
                                            unsigned* __restrict__ bw, int lane) {
    unsigned keep = 0;
    #pragma unroll
    for (int u8 = 0; u8 < 32; u8 += 8) {
        float sv[8];
        #pragma unroll
        for (int u = 0; u < 8; u++) {
            const int st = u8 + u;
            v = __fmaf_rn(v, 0.95f, z[st]);
            bool sp = (v >= 1.0f);
            sv[u] = sp ? 1.0f : 0.0f;
            unsigned bal = __ballot_sync(0xffffffffu, sp);
            keep = (lane == st) ? bal : keep;
            v = sp ? 0.0f : v;
        }
        *(float4*)(so + tbase + u8)     = make_float4(sv[0], sv[1], sv[2], sv[3]);
        *(float4*)(so + tbase + u8 + 4) = make_float4(sv[4], sv[5], sv[6], sv[7]);
    }
    bw[(size_t)(tbase + lane) * (CHID/32)] = keep;  // one scattered STG per 32 steps
}

__device__ __forceinline__ void proc32(float& v, const float (&z)[32],
                                       int tbase, float* __restrict__ so) {
    #pragma unroll
    for (int u8 = 0; u8 < 32; u8 += 8) {
        float sv[8];
        #pragma unroll
        for (int u = 0; u < 8; u++) {
            v = __fmaf_rn(v, 0.95f, z[u8 + u]);
            bool sp = (v >= 1.0f);
            sv[u] = sp ? 1.0f : 0.0f;
            v = sp ? 0.0f : v;
        }
        *(float4*)(so + tbase + u8)     = make_float4(sv[0], sv[1], sv[2], sv[3]);
        *(float4*)(so + tbase + u8 + 4) = make_float4(sv[4], sv[5], sv[6], sv[7]);
    }
}

// =====================================================================
// K2: layer-1 LIF scan. 16384 threads, block=64 (256 CTAs).
// 4 rotating 32-step register buffers (prefetch distance 3).
// =====================================================================
#define LD32(dst, zp, t) { _Pragma("unroll") \
    for (int u = 0; u < 32; u++) dst[u] = __ldg(zp + (size_t)((t) + u) * CHID); }

__global__ __launch_bounds__(64) void k2_scan1(float* __restrict__ out) {
    const int gid  = blockIdx.x * 64 + threadIdx.x;   // 0..16383
    const int b    = gid >> 8;
    const int o    = gid & 255;
    const int lane = o & 31;
    const float* z  = g_z1 + (size_t)b * TLEN * CHID + o;
    float*       so = out + ((size_t)b * CHID + o) * TLEN;
    unsigned*    bw = g_s1bits + (size_t)b * TLEN * (CHID/32) + (o >> 5);

    float A[32], B[32], C[32], D[32];
    float v = 0.0f;
    LD32(A, z, 0); LD32(B, z, 32); LD32(C, z, 64);

    for (int bi = 0; bi < 64; bi += 4) {
        const int t = bi * 32;
        if (bi + 3 < 64) LD32(D, z, t + 96);
        proc32_bits(v, A, t, so, bw, lane);
        if (bi + 4 < 64) LD32(A, z, t + 128);
        proc32_bits(v, B, t + 32, so, bw, lane);
        if (bi + 5 < 64) LD32(B, z, t + 160);
        proc32_bits(v, C, t + 64, so, bw, lane);
        if (bi + 6 < 64) LD32(C, z, t + 192);
        proc32_bits(v, D, t + 96, so, bw, lane);
    }
}

// =====================================================================
// K3: layer-2 sparse GEMM from spike bits. CTA = (t-chunk 64, b);
// 768 threads = 8 groups x 96 (3 full warps -> warp-uniform masks,
// 24 warps/SM at 1 CTA -> latency hidden).
// uint32 BYTE-offset lists (o*324, w2t stride 81 floats), dummy row 256.
// Two timesteps per iteration -> 2 independent FADD chains.
// =====================================================================
#define K3_T 64
__global__ __launch_bounds__(768) void k3_gemm2(const float* __restrict__ W2) {
    extern __shared__ char sm[];
    float*    w2t    = (float*)sm;                   // [257][81]+pad = 83344 B
    unsigned* lists  = (unsigned*)(sm + 83344);      // [64][264] u32 = 67584 B
    int*      counts = (int*)(sm + 150928);          // [64]

    const int tid = threadIdx.x;
    const int t0  = blockIdx.x * K3_T;
    const int b   = blockIdx.y;

    // W2 [80][256] row-major -> w2t[o*81 + j]; dummy row o=256 zeros
    for (int idx = tid; idx < COUT * CHID; idx += 768) {
        int j = idx / CHID, o = idx % CHID;
        w2t[o * 81 + j] = W2[idx];
    }
    if (tid < 100) w2t[256 * 81 + tid] = 0.0f;

    if (tid < K3_T) {  // build ascending o byte-offset list for step t0+tid
        const unsigned* sb = g_s1bits + (size_t)(b * TLEN + t0 + tid) * 8;
        unsigned* L = lists + tid * 264;
        int c = 0;
        #pragma unroll
        for (int w = 0; w < 8; w++) {
            unsigned m = sb[w];
            while (m) {
                int k = __ffs(m) - 1;
                m &= m - 1;
                L[c++] = (unsigned)(((w << 5) + k) * 324);
            }
        }
        while (c & 3) L[c++] = (unsigned)(256 * 324);
        counts[tid] = c;
    }
    __syncthreads();

    const int grp = tid / 96;            // 0..7 (3 full warps each)
    const int r   = tid % 96;            // j = r (r>=80 compute-only shadows)
    const char* wb = (const char*)w2t + r * 4;
    float* zo = g_z2 + ((size_t)b * TLEN + t0) * COUT;

    for (int q = grp; q < K3_T / 2; q += 8) {
        const int tt = 2 * q;
        const unsigned* L0 = lists + tt * 264;
        const unsigned* L1 = L0 + 264;
        const int c0 = counts[tt], c1 = counts[tt + 1];
        const int cmin = c0 < c1 ? c0 : c1;
        float a0 = 0.0f, a1 = 0.0f;
        int p = 0;
        for (; p < cmin; p += 4) {         // interleaved chains
            uint4 e0 = *(const uint4*)(L0 + p);
            uint4 e1 = *(const uint4*)(L1 + p);
            a0 += *(const float*)(wb + e0.x);  a1 += *(const float*)(wb + e1.x);
            a0 += *(const float*)(wb + e0.y);  a1 += *(const float*)(wb + e1.y);
            a0 += *(const float*)(wb + e0.z);  a1 += *(const float*)(wb + e1.z);
            a0 += *(const float*)(wb + e0.w);  a1 += *(const float*)(wb + e1.w);
        }
        for (; p < c0; p += 4) {
            uint4 e0 = *(const uint4*)(L0 + p);
            a0 += *(const float*)(wb + e0.x);  a0 += *(const float*)(wb + e0.y);
            a0 += *(const float*)(wb + e0.z);  a0 += *(const float*)(wb + e0.w);
        }
        for (; p < c1; p += 4) {
            uint4 e1 = *(const uint4*)(L1 + p);
            a1 += *(const float*)(wb + e1.x);  a1 += *(const float*)(wb + e1.y);
            a1 += *(const float*)(wb + e1.z);  a1 += *(const float*)(wb + e1.w);
        }
        if (r < COUT) {
            zo[(size_t)tt * COUT + r]       = a0;
            zo[(size_t)(tt + 1) * COUT + r] = a1;
        }
    }
}

// =====================================================================
// K4: layer-2 LIF scan. 5120 threads, block=32 (160 CTAs).
// =====================================================================
#define LD32B(dst, zp, t) { _Pragma("unroll") \
    for (int u = 0; u < 32; u++) dst[u] = __ldg(zp + (size_t)((t) + u) * COUT); }

__global__ __launch_bounds__(32) void k4_scan2(float* __restrict__ out) {
    const int gid = blockIdx.x * 32 + threadIdx.x;   // 0..5119
    const int b = gid / COUT;
    const int j = gid % COUT;
    const float* z  = g_z2 + (size_t)b * TLEN * COUT + j;
    float*       so = out + (size_t)BATCH * CHID * TLEN
                          + ((size_t)b * COUT + j) * TLEN;

    float A[32], B[32], C[32], D[32];
    float v = 0.0f;
    LD32B(A, z, 0); LD32B(B, z, 32); LD32B(C, z, 64);

    for (int bi = 0; bi < 64; bi += 4) {
        const int t = bi * 32;
        if (bi + 3 < 64) LD32B(D, z, t + 96);
        proc32(v, A, t, so);
        if (bi + 4 < 64) LD32B(A, z, t + 128);
        proc32(v, B, t + 32, so);
        if (bi + 5 < 64) LD32B(B, z, t + 160);
        proc32(v, C, t + 64, so);
        if (bi + 6 < 64) LD32B(C, z, t + 192);
        proc32(v, D, t + 96, so);
    }
}

// =====================================================================
extern "C" void kernel_launch(void* const* d_in, const int* in_sizes, int n_in,
                              void* d_out, int out_size) {
    const float* x  = (const float*)d_in[0];   // [64, 96, 2048]
    const float* W1 = (const float*)d_in[1];   // [256, 96]
    const float* W2 = (const float*)d_in[2];   // [80, 256]
    float* out = (float*)d_out;                // spk1 ++ spk2

    const int smem1 = 99328 + 53248 + 512;     // 153088
    const int smem3 = 83344 + 67584 + 256;     // 151184
    cudaFuncSetAttribute(k1_gemm1, cudaFuncAttributeMaxDynamicSharedMemorySize, smem1);
    cudaFuncSetAttribute(k3_gemm2, cudaFuncAttributeMaxDynamicSharedMemorySize, smem3);

    k0_xbits<<<(BATCH * TLEN) / 256, 256>>>(x);
    k1_gemm1<<<dim3(TLEN / K1_T, BATCH), 1024, smem1>>>(W1);
    k2_scan1<<<(BATCH * CHID) / 64, 64>>>(out);
    k3_gemm2<<<dim3(TLEN / K3_T, BATCH), 768, smem3>>>(W2);
    k4_scan2<<<(BATCH * COUT) / 32, 32>>>(out);
}